// round 3
// baseline (speedup 1.0000x reference)
#include <cuda_runtime.h>
#include <math.h>

#define NB 2
#define NC 21
#define PP 4096
#define KS 71
#define KR 35
#define GEMM_CTAS 1024   // 6144 gemm warps / 6 warps per CTA
#define CONV_CTAS (NB * NC)

// ---------------- scratch (static device globals; no allocation) ----------------
__device__ float g_K[(size_t)NB * PP * PP];     // 134 MB fp32
__device__ float g_feat[NB * 5 * PP];
__device__ float g_h[NB * PP];
__device__ float g_U[NB * NC * PP];
__device__ float g_q[NB * NC * PP];
__device__ float g_qbf[NB * NC * PP];
__device__ float g_qsf[NB * NC * PP];
__device__ float g_g1d[KS];

// ---------------- packed f32x2 FMA (2 MACs / inst) ----------------
__device__ __forceinline__ void fma2(float2& a, float bx, float by, float cx, float cy) {
    float2 b = make_float2(bx, by);
    float2 c = make_float2(cx, cy);
    unsigned long long* pa = reinterpret_cast<unsigned long long*>(&a);
    unsigned long long bb = *reinterpret_cast<unsigned long long*>(&b);
    unsigned long long cc = *reinterpret_cast<unsigned long long*>(&c);
    asm("fma.rn.f32x2 %0, %1, %2, %0;" : "+l"(*pa) : "l"(bb), "l"(cc));
}

// ---------------- init: U=log(clip(unary)), features+h, separable 1D kernel ----------------
__global__ void k_init(const float* __restrict__ unary, const float* __restrict__ ref,
                       const float* __restrict__ kstd, const float* __restrict__ gk) {
    int t = blockIdx.x * blockDim.x + threadIdx.x;
    if (t < NB * NC * PP) {
        float u = unary[t];
        u = fminf(fmaxf(u, 1e-5f), 1.0f);
        g_U[t] = logf(u);
    }
    if (t < NB * PP) {
        int n = t / PP, p = t % PP;
        int y = p >> 6, x = p & 63;
        float f[5];
        f[0] = (float)y / kstd[0];
        f[1] = (float)x / kstd[1];
        f[2] = ref[(n * 3 + 0) * PP + p] / kstd[2];
        f[3] = ref[(n * 3 + 1) * PP + p] / kstd[3];
        f[4] = ref[(n * 3 + 2) * PP + p] / kstd[4];
        float h = 0.f;
#pragma unroll
        for (int d = 0; d < 5; ++d) {
            g_feat[(n * 5 + d) * PP + p] = f[d];
            h = fmaf(f[d], f[d], h);
        }
        g_h[n * PP + p] = -0.5f * h;
    }
    if (blockIdx.x == 0) {
        __shared__ float s[128];
        int tt = threadIdx.x;
        float v = 0.f;
        if (tt < 128) {
            v = (tt < KS) ? gk[KR * KS + tt] : 0.f;  // channel 0, center row
            s[tt] = v;
        }
        __syncthreads();
        for (int o = 64; o; o >>= 1) {
            if (tt < o) s[tt] += s[tt + o];
            __syncthreads();
        }
        if (tt < KS) g_g1d[tt] = v / s[0];
    }
}

// ---------------- build K (symmetric: upper-triangle tiles, smem transpose) ----------------
__global__ void k_buildK() {
    int bj = blockIdx.x, bi = blockIdx.y, n = blockIdx.z;
    if (bj < bi) return;
    __shared__ float sfi[5][64], sfj[5][64], shi[64], shj[64];
    __shared__ float tile[64][65];
    int tid = threadIdx.x;
    if (tid < 64) {
        int pi = bi * 64 + tid, pj = bj * 64 + tid;
#pragma unroll
        for (int d = 0; d < 5; ++d) {
            sfi[d][tid] = g_feat[(n * 5 + d) * PP + pi];
            sfj[d][tid] = g_feat[(n * 5 + d) * PP + pj];
        }
        shi[tid] = g_h[n * PP + pi];
        shj[tid] = g_h[n * PP + pj];
    }
    __syncthreads();
    for (int e = tid; e < 64 * 64; e += 256) {
        int i = e >> 6, j = e & 63;
        float a = shi[i] + shj[j];
#pragma unroll
        for (int d = 0; d < 5; ++d) a = fmaf(sfi[d][i], sfj[d][j], a);
        tile[i][j] = __expf(a);
    }
    __syncthreads();
    size_t base = (size_t)n * PP * PP;
    for (int e = tid; e < 64 * 64; e += 256) {
        int i = e >> 6, j = e & 63;
        g_K[base + (size_t)(bi * 64 + i) * PP + (bj * 64 + j)] = tile[i][j];
    }
    if (bi != bj) {
        for (int e = tid; e < 64 * 64; e += 256) {
            int i = e >> 6, j = e & 63;
            g_K[base + (size_t)(bj * 64 + i) * PP + (bi * 64 + j)] = tile[j][i];
        }
    }
}

// ---------------- softmax / update: q = softmax(U [+ 4 qbf + 2 qsf]) ----------------
__global__ void k_softmax(int usebq, float* __restrict__ extout) {
    int t = blockIdx.x * blockDim.x + threadIdx.x;
    if (t >= NB * PP) return;
    int n = t >> 12, p = t & 4095;
    float v[NC];
    float m = -1e30f;
#pragma unroll
    for (int c = 0; c < NC; ++c) {
        int idx = (n * NC + c) * PP + p;
        float a = g_U[idx];
        if (usebq) a = a + 4.0f * g_qbf[idx] + 2.0f * g_qsf[idx];
        v[c] = a;
        m = fmaxf(m, a);
    }
    float s = 0.f;
#pragma unroll
    for (int c = 0; c < NC; ++c) {
        v[c] = __expf(v[c] - m);
        s += v[c];
    }
    float inv = 1.0f / s;
#pragma unroll
    for (int c = 0; c < NC; ++c) {
        int idx = (n * NC + c) * PP + p;
        float r = v[c] * inv;
        g_q[idx] = r;
        if (extout) extout[idx] = r;
    }
}

// ---------------- fused iteration kernel: GEMM CTAs + conv CTAs ----------------
// GEMM: qbf[n][c][p] = sum_q K[n][p][q] * q[n][c][q]
//   warp = (batch, rowblock of 4, channel-group of 7). 6 warps/CTA, 1024 CTAs.
// Conv: separable 71-tap depthwise spatial filter on q -> qsf. 42 CTAs.
__global__ void __launch_bounds__(192, 3) k_iter() {
    int wid = threadIdx.x >> 5, lane = threadIdx.x & 31;

    if (blockIdx.x < GEMM_CTAS) {
        int gidx = blockIdx.x * 6 + wid;            // 0..6143
        int n = (gidx >= 3072) ? 1 : 0;
        int r = gidx - n * 3072;
        int cg = r % 3;                              // channel group (7 channels)
        int pbase = (r / 3) * 4;                     // 4 rows per warp

        const float4* K0 = (const float4*)(g_K + (size_t)n * PP * PP + (size_t)pbase * PP);
        const float4* qb = (const float4*)(g_q + (n * NC + cg * 7) * PP);

        float2 acc[4][7];
#pragma unroll
        for (int i = 0; i < 4; ++i)
#pragma unroll
            for (int c = 0; c < 7; ++c) acc[i][c] = make_float2(0.f, 0.f);

        for (int qc = 0; qc < 32; ++qc) {
            int off = (qc << 5) + lane;
            float4 w0 = K0[off];
            float4 w1 = K0[off + 1024];
            float4 w2 = K0[off + 2048];
            float4 w3 = K0[off + 3072];
#pragma unroll
            for (int c = 0; c < 7; ++c) {
                float4 qv = qb[c * 1024 + off];
                fma2(acc[0][c], w0.x, w0.y, qv.x, qv.y);
                fma2(acc[0][c], w0.z, w0.w, qv.z, qv.w);
                fma2(acc[1][c], w1.x, w1.y, qv.x, qv.y);
                fma2(acc[1][c], w1.z, w1.w, qv.z, qv.w);
                fma2(acc[2][c], w2.x, w2.y, qv.x, qv.y);
                fma2(acc[2][c], w2.z, w2.w, qv.z, qv.w);
                fma2(acc[3][c], w3.x, w3.y, qv.x, qv.y);
                fma2(acc[3][c], w3.z, w3.w, qv.z, qv.w);
            }
        }

#pragma unroll
        for (int i = 0; i < 4; ++i) {
#pragma unroll
            for (int c = 0; c < 7; ++c) {
                float s = acc[i][c].x + acc[i][c].y;
#pragma unroll
                for (int o = 16; o; o >>= 1) s += __shfl_xor_sync(0xFFFFFFFFu, s, o);
                if (lane == 0) g_qbf[(n * NC + cg * 7 + c) * PP + pbase + i] = s;
            }
        }
    } else {
        // -------- conv branch --------
        __shared__ float sin_[PP];
        __shared__ float stmp[PP];
        __shared__ float sg[KS];
        int cid = blockIdx.x - GEMM_CTAS;
        int c = cid % NC, n = cid / NC;
        int tid = threadIdx.x;
        if (tid < KS) sg[tid] = g_g1d[tid];
        const float* src = g_q + (n * NC + c) * PP;
        for (int i = tid; i < PP; i += 192) sin_[i] = src[i];
        __syncthreads();
        // horizontal pass
        for (int e = tid; e < PP; e += 192) {
            int y = e >> 6, x = e & 63;
            int lo = max(0, x - KR), hi = min(63, x + KR);
            float a = 0.f;
            for (int xx = lo; xx <= hi; ++xx) a = fmaf(sg[KR + xx - x], sin_[(y << 6) | xx], a);
            stmp[e] = a;
        }
        __syncthreads();
        // vertical pass
        float* dst = g_qsf + (n * NC + c) * PP;
        for (int e = tid; e < PP; e += 192) {
            int y = e >> 6, x = e & 63;
            int lo = max(0, y - KR), hi = min(63, y + KR);
            float a = 0.f;
            for (int yy = lo; yy <= hi; ++yy) a = fmaf(sg[KR + yy - y], stmp[(yy << 6) | x], a);
            dst[e] = a;
        }
    }
}

// ---------------- launch ----------------
extern "C" void kernel_launch(void* const* d_in, const int* in_sizes, int n_in,
                              void* d_out, int out_size) {
    (void)in_sizes; (void)n_in; (void)out_size;
    const float* unary = (const float*)d_in[0];
    const float* ref   = (const float*)d_in[1];
    const float* gk    = (const float*)d_in[2];
    const float* kstd  = (const float*)d_in[3];
    float* out = (float*)d_out;

    k_init<<<(NB * NC * PP + 255) / 256, 256>>>(unary, ref, kstd, gk);
    k_buildK<<<dim3(64, 64, NB), 256>>>();
    k_softmax<<<(NB * PP + 255) / 256, 256>>>(0, nullptr);  // q0 = softmax(U)

    for (int it = 0; it < 5; ++it) {
        k_iter<<<GEMM_CTAS + CONV_CTAS, 192>>>();
        bool last = (it == 4);
        k_softmax<<<(NB * PP + 255) / 256, 256>>>(1, last ? out : nullptr);
    }
}

// round 4
// speedup vs baseline: 1.1974x; 1.1974x over previous
#include <cuda_runtime.h>
#include <math.h>

#define NB 2
#define NC 21
#define PP 4096
#define KS 71
#define KR 35
#define KSPLIT 16
#define KCH 256          // 4096 / KSPLIT

// ---------------- scratch (static device globals; no allocation) ----------------
__device__ float g_K[(size_t)NB * PP * PP];          // 134 MB fp32
__device__ float g_feat[NB * 5 * PP];
__device__ float g_h[NB * PP];
__device__ float g_U[NB * NC * PP];
__device__ float g_q[NB * NC * PP];
__device__ float g_part[NB * NC * KSPLIT * PP];      // gemm partials (11 MB)
__device__ float g_tmp[NB * NC * PP];                // conv h-pass intermediate
__device__ float g_qsf[NB * NC * PP];                // conv result
__device__ float g_g1d[KS];

// ---------------- packed f32x2 FMA (2 MACs / inst) ----------------
__device__ __forceinline__ void fma2(float2& a, float bx, float by, float cx, float cy) {
    float2 b = make_float2(bx, by);
    float2 c = make_float2(cx, cy);
    unsigned long long* pa = reinterpret_cast<unsigned long long*>(&a);
    unsigned long long bb = *reinterpret_cast<unsigned long long*>(&b);
    unsigned long long cc = *reinterpret_cast<unsigned long long*>(&c);
    asm("fma.rn.f32x2 %0, %1, %2, %0;" : "+l"(*pa) : "l"(bb), "l"(cc));
}

// ---------------- init: U=log(clip(unary)), features+h, separable 1D kernel ----------------
__global__ void k_init(const float* __restrict__ unary, const float* __restrict__ ref,
                       const float* __restrict__ kstd, const float* __restrict__ gk) {
    int t = blockIdx.x * blockDim.x + threadIdx.x;
    if (t < NB * NC * PP) {
        float u = unary[t];
        u = fminf(fmaxf(u, 1e-5f), 1.0f);
        g_U[t] = logf(u);
    }
    if (t < NB * PP) {
        int n = t / PP, p = t % PP;
        int y = p >> 6, x = p & 63;
        float f[5];
        f[0] = (float)y / kstd[0];
        f[1] = (float)x / kstd[1];
        f[2] = ref[(n * 3 + 0) * PP + p] / kstd[2];
        f[3] = ref[(n * 3 + 1) * PP + p] / kstd[3];
        f[4] = ref[(n * 3 + 2) * PP + p] / kstd[4];
        float h = 0.f;
#pragma unroll
        for (int d = 0; d < 5; ++d) {
            g_feat[(n * 5 + d) * PP + p] = f[d];
            h = fmaf(f[d], f[d], h);
        }
        g_h[n * PP + p] = -0.5f * h;
    }
    if (blockIdx.x == 0) {
        __shared__ float s[128];
        int tt = threadIdx.x;
        float v = 0.f;
        if (tt < 128) {
            v = (tt < KS) ? gk[KR * KS + tt] : 0.f;  // channel 0, center row
            s[tt] = v;
        }
        __syncthreads();
        for (int o = 64; o; o >>= 1) {
            if (tt < o) s[tt] += s[tt + o];
            __syncthreads();
        }
        if (tt < KS) g_g1d[tt] = v / s[0];
    }
}

// ---------------- build K (symmetric: upper-triangle tiles, smem transpose) ----------------
__global__ void k_buildK() {
    int bj = blockIdx.x, bi = blockIdx.y, n = blockIdx.z;
    if (bj < bi) return;
    __shared__ float sfi[5][64], sfj[5][64], shi[64], shj[64];
    __shared__ float tile[64][65];
    int tid = threadIdx.x;
    if (tid < 64) {
        int pi = bi * 64 + tid, pj = bj * 64 + tid;
#pragma unroll
        for (int d = 0; d < 5; ++d) {
            sfi[d][tid] = g_feat[(n * 5 + d) * PP + pi];
            sfj[d][tid] = g_feat[(n * 5 + d) * PP + pj];
        }
        shi[tid] = g_h[n * PP + pi];
        shj[tid] = g_h[n * PP + pj];
    }
    __syncthreads();
    for (int e = tid; e < 64 * 64; e += 256) {
        int i = e >> 6, j = e & 63;
        float a = shi[i] + shj[j];
#pragma unroll
        for (int d = 0; d < 5; ++d) a = fmaf(sfi[d][i], sfj[d][j], a);
        tile[i][j] = __expf(a);
    }
    __syncthreads();
    size_t base = (size_t)n * PP * PP;
    for (int e = tid; e < 64 * 64; e += 256) {
        int i = e >> 6, j = e & 63;
        g_K[base + (size_t)(bi * 64 + i) * PP + (bj * 64 + j)] = tile[i][j];
    }
    if (bi != bj) {
        for (int e = tid; e < 64 * 64; e += 256) {
            int i = e >> 6, j = e & 63;
            g_K[base + (size_t)(bj * 64 + i) * PP + (bi * 64 + j)] = tile[j][i];
        }
    }
}

// ---------------- GEMM (+ fused horizontal conv pass) ----------------
// blockIdx: x = rowblock (32), y = k-slice (0..15) or 16 = conv-h duty, z = batch
// GEMM CTA: 128 threads, thread = one K row p, k-range of 256.
// q chunk staged in smem; all sq reads are warp-uniform (broadcast).
__global__ void __launch_bounds__(128, 6) k_gemm() {
    __shared__ float sq[NC][KCH];

    int n = blockIdx.z;
    if (blockIdx.y < KSPLIT) {
        int slice = blockIdx.y, rb = blockIdx.x;
        int k0 = slice * KCH;
        const float* qsrc = g_q + n * NC * PP;
        for (int idx = threadIdx.x; idx < NC * (KCH / 4); idx += 128) {
            int c = idx / (KCH / 4), kk = idx % (KCH / 4);
            ((float4*)sq[c])[kk] = ((const float4*)(qsrc + c * PP + k0))[kk];
        }
        __syncthreads();

        int p = rb * 128 + threadIdx.x;
        const float4* Kr = (const float4*)(g_K + (size_t)n * PP * PP + (size_t)p * PP + k0);

        float2 acc[NC];
#pragma unroll
        for (int c = 0; c < NC; ++c) acc[c] = make_float2(0.f, 0.f);

#pragma unroll 2
        for (int i = 0; i < KCH / 4; ++i) {
            float4 kv = Kr[i];
#pragma unroll
            for (int c = 0; c < NC; ++c) {
                float4 qv = ((const float4*)sq[c])[i];
                fma2(acc[c], kv.x, kv.y, qv.x, qv.y);
                fma2(acc[c], kv.z, kv.w, qv.z, qv.w);
            }
        }
#pragma unroll
        for (int c = 0; c < NC; ++c)
            g_part[((n * NC + c) * KSPLIT + slice) * PP + p] = acc[c].x + acc[c].y;
    } else {
        // -------- horizontal conv pass: rides along with the GEMM wave --------
        __shared__ float sg[KS];
        if (threadIdx.x < KS) sg[threadIdx.x] = g_g1d[threadIdx.x];
        __syncthreads();
        // 64 such CTAs (32 rowblocks x 2 batches) x 128 threads cover NB*NC*PP px
        int slot = (n * 32 + blockIdx.x) * 128 + threadIdx.x;  // 0..8191
        for (int t = slot; t < NB * NC * PP; t += 8192) {
            int e = t & 4095;
            int x = e & 63;
            const float* row = g_q + (t - x);  // row base within plane
            float a = 0.f;
#pragma unroll 8
            for (int j = 0; j < KS; ++j) {
                int xx = x - KR + j;
                if ((unsigned)xx < 64u) a = fmaf(sg[j], row[xx], a);
            }
            g_tmp[t] = a;
        }
    }
}

// ---------------- vertical conv pass ----------------
__global__ void k_convv() {
    __shared__ float sg[KS];
    if (threadIdx.x < KS) sg[threadIdx.x] = g_g1d[threadIdx.x];
    __syncthreads();
    int t = blockIdx.x * blockDim.x + threadIdx.x;
    if (t >= NB * NC * PP) return;
    int e = t & 4095;
    int y = e >> 6, x = e & 63;
    const float* plane = g_tmp + (t - e);
    float a = 0.f;
#pragma unroll 8
    for (int j = 0; j < KS; ++j) {
        int yy = y - KR + j;
        if ((unsigned)yy < 64u) a = fmaf(sg[j], plane[(yy << 6) | x], a);
    }
    g_qsf[t] = a;
}

// ---------------- softmax / update: q = softmax(U [+ 4*sum(part) + 2*qsf]) ----------------
__global__ void k_softmax(int usebq, float* __restrict__ extout) {
    int t = blockIdx.x * blockDim.x + threadIdx.x;
    if (t >= NB * PP) return;
    int n = t >> 12, p = t & 4095;
    float v[NC];
    float m = -1e30f;
#pragma unroll
    for (int c = 0; c < NC; ++c) {
        int idx = (n * NC + c) * PP + p;
        float a = g_U[idx];
        if (usebq) {
            float bf = 0.f;
            const float* pp = g_part + (size_t)(n * NC + c) * KSPLIT * PP + p;
#pragma unroll
            for (int s = 0; s < KSPLIT; ++s) bf += pp[s * PP];
            a = a + 4.0f * bf + 2.0f * g_qsf[idx];
        }
        v[c] = a;
        m = fmaxf(m, a);
    }
    float s = 0.f;
#pragma unroll
    for (int c = 0; c < NC; ++c) {
        v[c] = __expf(v[c] - m);
        s += v[c];
    }
    float inv = 1.0f / s;
#pragma unroll
    for (int c = 0; c < NC; ++c) {
        int idx = (n * NC + c) * PP + p;
        float r = v[c] * inv;
        g_q[idx] = r;
        if (extout) extout[idx] = r;
    }
}

// ---------------- launch ----------------
extern "C" void kernel_launch(void* const* d_in, const int* in_sizes, int n_in,
                              void* d_out, int out_size) {
    (void)in_sizes; (void)n_in; (void)out_size;
    const float* unary = (const float*)d_in[0];
    const float* ref   = (const float*)d_in[1];
    const float* gk    = (const float*)d_in[2];
    const float* kstd  = (const float*)d_in[3];
    float* out = (float*)d_out;

    k_init<<<(NB * NC * PP + 255) / 256, 256>>>(unary, ref, kstd, gk);
    k_buildK<<<dim3(64, 64, NB), 256>>>();
    k_softmax<<<128, 64>>>(0, nullptr);  // q0 = softmax(U)

    for (int it = 0; it < 5; ++it) {
        k_gemm<<<dim3(32, KSPLIT + 1, NB), 128>>>();       // GEMM + fused conv-h
        k_convv<<<(NB * NC * PP + 255) / 256, 256>>>();
        bool last = (it == 4);
        k_softmax<<<128, 64>>>(1, last ? out : nullptr);
    }
}

// round 5
// speedup vs baseline: 1.7327x; 1.4471x over previous
#include <cuda_runtime.h>
#include <math.h>

#define NB 2
#define NC 21
#define NCP 11           // channel pairs (last padded)
#define PP 4096
#define KS 71
#define KR 35
#define KSPL 32
#define KCH 128          // 4096 / KSPL
#define GEMM_CTAS (NB * 8 * KSPL)   // 512: 8 rowblocks x 32 kslices x 2 batches
#define CONV_CTAS (NB * NC)

// ---------------- scratch (static device globals; no allocation) ----------------
__device__ float g_K[(size_t)NB * PP * PP];          // 134 MB fp32, symmetric
__device__ float g_feat[NB * 5 * PP];
__device__ float g_h[NB * PP];
__device__ float g_U[NB * NC * PP];
__device__ float g_q[NB * NC * PP];                  // q, channel-major (conv reads this)
__device__ float2 g_qpair[NB * NCP * PP];            // q packed by channel pair (gemm reads this)
__device__ float g_part[NB * NC * KSPL * PP];        // gemm partials (22 MB)
__device__ float g_qsf[NB * NC * PP];                // spatial conv result
__device__ float g_g1d[KS];

// ---------------- packed f32x2 FMA: acc.x += bx*cx, acc.y += by*cy ----------------
__device__ __forceinline__ void fma2(float2& a, float bx, float by, float cx, float cy) {
    float2 b = make_float2(bx, by);
    float2 c = make_float2(cx, cy);
    unsigned long long* pa = reinterpret_cast<unsigned long long*>(&a);
    unsigned long long bb = *reinterpret_cast<unsigned long long*>(&b);
    unsigned long long cc = *reinterpret_cast<unsigned long long*>(&c);
    asm("fma.rn.f32x2 %0, %1, %2, %0;" : "+l"(*pa) : "l"(bb), "l"(cc));
}

// ---------------- init: U=log(clip(unary)), features+h, separable 1D kernel ----------------
__global__ void k_init(const float* __restrict__ unary, const float* __restrict__ ref,
                       const float* __restrict__ kstd, const float* __restrict__ gk) {
    int t = blockIdx.x * blockDim.x + threadIdx.x;
    if (t < NB * NC * PP) {
        float u = unary[t];
        u = fminf(fmaxf(u, 1e-5f), 1.0f);
        g_U[t] = logf(u);
    }
    if (t < NB * PP) {
        int n = t / PP, p = t % PP;
        int y = p >> 6, x = p & 63;
        float f[5];
        f[0] = (float)y / kstd[0];
        f[1] = (float)x / kstd[1];
        f[2] = ref[(n * 3 + 0) * PP + p] / kstd[2];
        f[3] = ref[(n * 3 + 1) * PP + p] / kstd[3];
        f[4] = ref[(n * 3 + 2) * PP + p] / kstd[4];
        float h = 0.f;
#pragma unroll
        for (int d = 0; d < 5; ++d) {
            g_feat[(n * 5 + d) * PP + p] = f[d];
            h = fmaf(f[d], f[d], h);
        }
        g_h[n * PP + p] = -0.5f * h;
    }
    if (blockIdx.x == 0) {
        __shared__ float s[128];
        int tt = threadIdx.x;
        float v = 0.f;
        if (tt < 128) {
            v = (tt < KS) ? gk[KR * KS + tt] : 0.f;  // channel 0, center row
            s[tt] = v;
        }
        __syncthreads();
        for (int o = 64; o; o >>= 1) {
            if (tt < o) s[tt] += s[tt + o];
            __syncthreads();
        }
        if (tt < KS) g_g1d[tt] = v / s[0];
    }
}

// ---------------- build K (symmetric: upper-triangle tiles, smem transpose) ----------------
__global__ void k_buildK() {
    int bj = blockIdx.x, bi = blockIdx.y, n = blockIdx.z;
    if (bj < bi) return;
    __shared__ float sfi[5][64], sfj[5][64], shi[64], shj[64];
    __shared__ float tile[64][65];
    int tid = threadIdx.x;
    if (tid < 64) {
        int pi = bi * 64 + tid, pj = bj * 64 + tid;
#pragma unroll
        for (int d = 0; d < 5; ++d) {
            sfi[d][tid] = g_feat[(n * 5 + d) * PP + pi];
            sfj[d][tid] = g_feat[(n * 5 + d) * PP + pj];
        }
        shi[tid] = g_h[n * PP + pi];
        shj[tid] = g_h[n * PP + pj];
    }
    __syncthreads();
    for (int e = tid; e < 64 * 64; e += 256) {
        int i = e >> 6, j = e & 63;
        float a = shi[i] + shj[j];
#pragma unroll
        for (int d = 0; d < 5; ++d) a = fmaf(sfi[d][i], sfj[d][j], a);
        tile[i][j] = __expf(a);
    }
    __syncthreads();
    size_t base = (size_t)n * PP * PP;
    for (int e = tid; e < 64 * 64; e += 256) {
        int i = e >> 6, j = e & 63;
        g_K[base + (size_t)(bi * 64 + i) * PP + (bj * 64 + j)] = tile[i][j];
    }
    if (bi != bj) {
        for (int e = tid; e < 64 * 64; e += 256) {
            int i = e >> 6, j = e & 63;
            g_K[base + (size_t)(bj * 64 + i) * PP + (bi * 64 + j)] = tile[j][i];
        }
    }
}

// ---------------- fused iteration: GEMM CTAs + spatial-conv CTAs ----------------
// GEMM (coalesced via K symmetry): thread owns 4 output rows p0..p0+3 and reads
// K[k][p0..p0+3] as one coalesced float4. q comes as channel-pair packed float4
// broadcasts from smem. acc[row][cpair] in packed f32x2.
__global__ void __launch_bounds__(128, 4) k_iter() {
    __shared__ __align__(16) float s_buf[2 * PP + 128];   // union: gemm sq4 | conv planes

    int tid = threadIdx.x;
    if (blockIdx.x < GEMM_CTAS) {
        int bid = blockIdx.x;
        int n = bid >> 8;
        int rem = bid & 255;
        int rb = rem >> 5;            // 0..7 rowblock (512 rows)
        int slice = rem & 31;         // k-slice
        int k0 = slice * KCH;

        // stage packed q chunk: sq4[cp][j] = (q2c(k0+2j), q2c1(k0+2j), q2c(k0+2j+1), q2c1(k0+2j+1))
        float4* sq4 = (float4*)s_buf;                       // [NCP][KCH/2] = 704 float4
        const float4* qp = (const float4*)(g_qpair + (size_t)n * NCP * PP);
        for (int idx = tid; idx < NCP * (KCH / 2); idx += 128) {
            int cp = idx >> 6, j = idx & 63;
            sq4[idx] = qp[cp * (PP / 2) + (k0 >> 1) + j];
        }
        __syncthreads();

        int p0 = rb * 512 + tid * 4;
        const float* Kp = g_K + (size_t)n * PP * PP + (size_t)k0 * PP + p0;

        float2 acc[4][NCP];
#pragma unroll
        for (int r = 0; r < 4; ++r)
#pragma unroll
            for (int cp = 0; cp < NCP; ++cp) acc[r][cp] = make_float2(0.f, 0.f);

#pragma unroll 2
        for (int j = 0; j < KCH / 2; ++j) {
            float4 Ka = *(const float4*)(Kp);
            float4 Kb = *(const float4*)(Kp + PP);
            Kp += 2 * PP;
#pragma unroll
            for (int cp = 0; cp < NCP; ++cp) {
                float4 qv = sq4[(cp << 6) + j];
                fma2(acc[0][cp], Ka.x, Ka.x, qv.x, qv.y);
                fma2(acc[0][cp], Kb.x, Kb.x, qv.z, qv.w);
                fma2(acc[1][cp], Ka.y, Ka.y, qv.x, qv.y);
                fma2(acc[1][cp], Kb.y, Kb.y, qv.z, qv.w);
                fma2(acc[2][cp], Ka.z, Ka.z, qv.x, qv.y);
                fma2(acc[2][cp], Kb.z, Kb.z, qv.z, qv.w);
                fma2(acc[3][cp], Ka.w, Ka.w, qv.x, qv.y);
                fma2(acc[3][cp], Kb.w, Kb.w, qv.z, qv.w);
            }
        }

#pragma unroll
        for (int r = 0; r < 4; ++r) {
            int p = p0 + r;
#pragma unroll
            for (int cp = 0; cp < NCP; ++cp) {
                g_part[((n * NC + 2 * cp) * KSPL + slice) * PP + p] = acc[r][cp].x;
                if (cp < NCP - 1)
                    g_part[((n * NC + 2 * cp + 1) * KSPL + slice) * PP + p] = acc[r][cp].y;
            }
        }
    } else {
        // -------- spatial conv (separable 71-tap), one CTA per (n,c) plane --------
        float* sin_ = s_buf;
        float* stmp = s_buf + PP;
        float* sg = s_buf + 2 * PP;
        int cid = blockIdx.x - GEMM_CTAS;
        int c = cid % NC, n = cid / NC;
        if (tid < KS) sg[tid] = g_g1d[tid];
        const float* src = g_q + (n * NC + c) * PP;
        for (int i = tid; i < PP; i += 128) sin_[i] = src[i];
        __syncthreads();
        for (int e = tid; e < PP; e += 128) {
            int y = e >> 6, x = e & 63;
            int lo = max(0, x - KR), hi = min(63, x + KR);
            float a = 0.f;
            for (int xx = lo; xx <= hi; ++xx) a = fmaf(sg[KR + xx - x], sin_[(y << 6) | xx], a);
            stmp[e] = a;
        }
        __syncthreads();
        float* dst = g_qsf + (n * NC + c) * PP;
        for (int e = tid; e < PP; e += 128) {
            int y = e >> 6, x = e & 63;
            int lo = max(0, y - KR), hi = min(63, y + KR);
            float a = 0.f;
            for (int yy = lo; yy <= hi; ++yy) a = fmaf(sg[KR + yy - y], stmp[(yy << 6) | x], a);
            dst[e] = a;
        }
    }
}

// ---------------- softmax / update: q = softmax(U [+ 4*sum(part) + 2*qsf]) ----------------
__global__ void k_softmax(int usebq, float* __restrict__ extout) {
    int t = blockIdx.x * blockDim.x + threadIdx.x;
    if (t >= NB * PP) return;
    int n = t >> 12, p = t & 4095;
    float v[NC];
    float m = -1e30f;
#pragma unroll
    for (int c = 0; c < NC; ++c) {
        int idx = (n * NC + c) * PP + p;
        float a = g_U[idx];
        if (usebq) {
            float bf = 0.f;
            const float* pp = g_part + (size_t)(n * NC + c) * KSPL * PP + p;
#pragma unroll
            for (int s = 0; s < KSPL; ++s) bf += pp[s * PP];
            a = a + 4.0f * bf + 2.0f * g_qsf[idx];
        }
        v[c] = a;
        m = fmaxf(m, a);
    }
    float s = 0.f;
#pragma unroll
    for (int c = 0; c < NC; ++c) {
        v[c] = __expf(v[c] - m);
        s += v[c];
    }
    float inv = 1.0f / s;
#pragma unroll
    for (int c = 0; c < NC; ++c) {
        int idx = (n * NC + c) * PP + p;
        float r = v[c] * inv;
        g_q[idx] = r;
        if (extout) extout[idx] = r;
    }
    // packed channel-pair layout for the gemm
#pragma unroll
    for (int cp = 0; cp < NCP; ++cp) {
        float a = v[2 * cp] * inv;
        float b = (2 * cp + 1 < NC) ? v[2 * cp + 1] * inv : 0.f;
        g_qpair[(n * NCP + cp) * PP + p] = make_float2(a, b);
    }
}

// ---------------- launch ----------------
extern "C" void kernel_launch(void* const* d_in, const int* in_sizes, int n_in,
                              void* d_out, int out_size) {
    (void)in_sizes; (void)n_in; (void)out_size;
    const float* unary = (const float*)d_in[0];
    const float* ref   = (const float*)d_in[1];
    const float* gk    = (const float*)d_in[2];
    const float* kstd  = (const float*)d_in[3];
    float* out = (float*)d_out;

    k_init<<<(NB * NC * PP + 255) / 256, 256>>>(unary, ref, kstd, gk);
    k_buildK<<<dim3(64, 64, NB), 256>>>();
    k_softmax<<<128, 64>>>(0, nullptr);  // q0 = softmax(U)

    for (int it = 0; it < 5; ++it) {
        k_iter<<<GEMM_CTAS + CONV_CTAS, 128>>>();
        bool last = (it == 4);
        k_softmax<<<128, 64>>>(1, last ? out : nullptr);
    }
}